// round 4
// baseline (speedup 1.0000x reference)
#include <cuda_runtime.h>

#define BB 32
#define KK 10
#define NN 128
#define FF 512
#define NITER 30
#define LRc 0.5f
#define RHOc 10.0f

// ---- scratch (static device globals: allocation-free) ----
static __device__ float g_C[BB * NN * NN];          // 2 MB cost matrix
static __device__ float g_Pp[2][BB * KK * 2 * NN];  // double-buffered partial col sums
static __device__ float g_costp[2][BB * KK * 2];    // partial costs
static __device__ float g_a0[BB * KK];
static __device__ float g_xn[BB * NN];
static __device__ unsigned int g_cnt[BB];           // per-b monotonic barrier counter

__device__ __forceinline__ float wsum(float v) {
#pragma unroll
    for (int o = 16; o; o >>= 1) v += __shfl_xor_sync(0xffffffffu, v, o);
    return v;
}
__device__ __forceinline__ float hsum8(float v) {
#pragma unroll
    for (int o = 4; o; o >>= 1) v += __shfl_xor_sync(0xffffffffu, v, o);
    return v;
}
__device__ __forceinline__ float hmax8(float v) {
#pragma unroll
    for (int o = 4; o; o >>= 1) v = fmaxf(v, __shfl_xor_sync(0xffffffffu, v, o));
    return v;
}

// ================= prologue A: gemm (bid<128) + xn & out-zero (bid>=128) ==========
__global__ void proA_kernel(const float* __restrict__ X, float* __restrict__ out) {
    if (blockIdx.x < 128) {
        int bid = blockIdx.x;
        int b = bid >> 2, q2 = bid & 3;
        int ti = (q2 >> 1) * 64, tj = (q2 & 1) * 64;
        __shared__ float As[16][64];
        __shared__ float Bs[16][64];
        const float* Xb = X + (size_t)b * NN * FF;
        int t = threadIdx.x;
        int lr = t >> 2, lq = t & 3;
        int tx = t & 15, ty = t >> 4;
        float acc[4][4];
#pragma unroll
        for (int i = 0; i < 4; i++)
#pragma unroll
            for (int j = 0; j < 4; j++) acc[i][j] = 0.f;

        for (int kc = 0; kc < FF; kc += 16) {
            float4 av = *(const float4*)(Xb + (size_t)(ti + lr) * FF + kc + lq * 4);
            float4 bv = *(const float4*)(Xb + (size_t)(tj + lr) * FF + kc + lq * 4);
            if (kc) __syncthreads();
            As[lq * 4 + 0][lr] = av.x; As[lq * 4 + 1][lr] = av.y;
            As[lq * 4 + 2][lr] = av.z; As[lq * 4 + 3][lr] = av.w;
            Bs[lq * 4 + 0][lr] = bv.x; Bs[lq * 4 + 1][lr] = bv.y;
            Bs[lq * 4 + 2][lr] = bv.z; Bs[lq * 4 + 3][lr] = bv.w;
            __syncthreads();
#pragma unroll
            for (int kk = 0; kk < 16; kk++) {
                float4 af = *(const float4*)&As[kk][ty * 4];
                float4 bf = *(const float4*)&Bs[kk][tx * 4];
                float a[4] = {af.x, af.y, af.z, af.w};
                float bb4[4] = {bf.x, bf.y, bf.z, bf.w};
#pragma unroll
                for (int i = 0; i < 4; i++)
#pragma unroll
                    for (int j = 0; j < 4; j++) acc[i][j] = fmaf(a[i], bb4[j], acc[i][j]);
            }
        }
#pragma unroll
        for (int i = 0; i < 4; i++) {
            float4 o; o.x = acc[i][0]; o.y = acc[i][1]; o.z = acc[i][2]; o.w = acc[i][3];
            *(float4*)(g_C + ((size_t)b * NN + ti + ty * 4 + i) * NN + tj + tx * 4) = o;
        }
    } else {
        int b = blockIdx.x - 128;
        int w = threadIdx.x >> 5, lane = threadIdx.x & 31;
        for (int l = w; l < NN; l += 8) {
            const float4* xr = (const float4*)(X + ((size_t)b * NN + l) * FF);
            float acc = 0.f;
#pragma unroll
            for (int q = 0; q < FF / 128; q++) {
                float4 v = xr[lane + 32 * q];
                acc += v.x * v.x + v.y * v.y + v.z * v.z + v.w * v.w;
            }
            acc = wsum(acc);
            if (lane == 0) g_xn[b * NN + l] = acc;
        }
        // zero the output (needed for last-iter atomicAdd combine)
        for (int i = threadIdx.x; i < KK * NN; i += 256)
            out[b * KK * NN + i] = 0.f;
    }
}

// ===== prologue B: C = clip(dist - diag_col, 0) in-place, row sums, a0, counter reset =====
__global__ void proB_kernel(const float* __restrict__ Q, const float* __restrict__ theta) {
    int b = blockIdx.x;
    __shared__ float xns[NN], dgv[NN], crow[NN];
    float* Gb = g_C + (size_t)b * NN * NN;
    int tid = threadIdx.x;
    if (tid < NN) {
        float xj = g_xn[b * NN + tid];
        xns[tid] = xj;
        dgv[tid] = xj + xj - 2.0f * Gb[tid * NN + tid];
    }
    __syncthreads();
    int w = tid >> 5, lane = tid & 31;
    for (int i = w; i < NN; i += 8) {
        float xi = xns[i];
        float4 g = *(float4*)(Gb + i * NN + lane * 4);
        float c0 = fmaxf(xi + xns[lane * 4 + 0] - 2.0f * g.x - dgv[lane * 4 + 0], 0.f);
        float c1 = fmaxf(xi + xns[lane * 4 + 1] - 2.0f * g.y - dgv[lane * 4 + 1], 0.f);
        float c2 = fmaxf(xi + xns[lane * 4 + 2] - 2.0f * g.z - dgv[lane * 4 + 2], 0.f);
        float c3 = fmaxf(xi + xns[lane * 4 + 3] - 2.0f * g.w - dgv[lane * 4 + 3], 0.f);
        *(float4*)(Gb + i * NN + lane * 4) = make_float4(c0, c1, c2, c3);
        float rs = wsum(c0 + c1 + c2 + c3);
        if (lane == 0) crow[i] = rs;
    }
    __syncthreads();
    // cost0_k = (1/128) * sum_l Q[l] * crow[l]  -> a0
    for (int k = w; k < KK; k += 8) {
        float v = 0.f;
        const float* Qr = Q + (b * KK + k) * NN;
        for (int i = lane; i < NN; i += 32) v = fmaf(Qr[i], crow[i], v);
        v = wsum(v);
        if (lane == 0) {
            float pen = v * (1.0f / NN) - theta[b * KK + k];
            g_a0[b * KK + k] = (pen > 0.f) ? (2.f * RHOc * pen) : 0.f;
        }
    }
    if (tid == 0) g_cnt[b] = 0u;
}

// ================= persistent solver: 2 CTAs per (b,k), 30 iterations =================
__global__ void __launch_bounds__(128, 5) solve_kernel(
        const float* __restrict__ Q, const float* __restrict__ theta,
        float* __restrict__ p_out) {
    __shared__ float S[64 * NN];     // 32 KB: this half's softmax probs
    __shared__ float w_s[NN];
    __shared__ float q_s[64];
    __shared__ float p_w[4 * NN];
    __shared__ float cst[4];
    __shared__ float a_s;

    int tid = threadIdx.x, warp = tid >> 5, lane = tid & 31;
    int rg = lane >> 3;             // row group 0-3 within warp
    int j0 = (lane & 7) * 16;       // 16 consecutive columns per thread
    int bkh = blockIdx.x, bk = bkh >> 1, half = bkh & 1;
    int b = bk / KK, k = bk - b * KK;

    const float* Cb = g_C + ((size_t)b * NN + half * 64) * NN;
    if (tid < 64) q_s[tid] = Q[bk * NN + half * 64 + tid];
    if (tid < NN) w_s[tid] = 0.f;   // iter 0: constant w cancels in (G - <s,G>)
    float th = theta[bk];
    float a = g_a0[bk];
    __syncthreads();

    for (int it = 0; it < NITER; ++it) {
        const bool first = (it == 0);
        const bool last = (it == NITER - 1);
        float pacc[16];
#pragma unroll
        for (int i = 0; i < 16; i++) pacc[i] = 0.f;
        float cacc = 0.f;

#pragma unroll
        for (int p = 0; p < 4; ++p) {
            int rl = p * 16 + warp * 4 + rg;     // local row 0..63
            float ql = q_s[rl];
            const float* cr = Cb + rl * NN + j0;
            float4 cv0 = __ldg((const float4*)cr);
            float4 cv1 = __ldg((const float4*)(cr + 4));
            float4 cv2 = __ldg((const float4*)(cr + 8));
            float4 cv3 = __ldg((const float4*)(cr + 12));
            float c[16] = {cv0.x, cv0.y, cv0.z, cv0.w, cv1.x, cv1.y, cv1.z, cv1.w,
                           cv2.x, cv2.y, cv2.z, cv2.w, cv3.x, cv3.y, cv3.z, cv3.w};
            float s[16];
            if (first) {
#pragma unroll
                for (int i = 0; i < 16; i++) s[i] = 0.0078125f;
            } else {
                float4 s0 = *(float4*)&S[rl * NN + j0];
                float4 s1 = *(float4*)&S[rl * NN + j0 + 4];
                float4 s2 = *(float4*)&S[rl * NN + j0 + 8];
                float4 s3 = *(float4*)&S[rl * NN + j0 + 12];
                s[0] = s0.x; s[1] = s0.y; s[2] = s0.z; s[3] = s0.w;
                s[4] = s1.x; s[5] = s1.y; s[6] = s1.z; s[7] = s1.w;
                s[8] = s2.x; s[9] = s2.y; s[10] = s2.z; s[11] = s2.w;
                s[12] = s3.x; s[13] = s3.y; s[14] = s3.z; s[15] = s3.w;
            }
            float4 w0 = *(float4*)&w_s[j0];
            float4 w1 = *(float4*)&w_s[j0 + 4];
            float4 w2 = *(float4*)&w_s[j0 + 8];
            float4 w3 = *(float4*)&w_s[j0 + 12];
            float wv[16] = {w0.x, w0.y, w0.z, w0.w, w1.x, w1.y, w1.z, w1.w,
                            w2.x, w2.y, w2.z, w2.w, w3.x, w3.y, w3.z, w3.w};

            float G[16], ms = 0.f;
#pragma unroll
            for (int i = 0; i < 16; i++) {
                G[i] = fmaf(-a, c[i], wv[i]);
                ms = fmaf(s[i], G[i], ms);
            }
            ms = hsum8(ms);

            float lq = LRc * ql;
            float d[16], M = -3.0e38f;
#pragma unroll
            for (int i = 0; i < 16; i++) {
                d[i] = (s[i] > 0.f) ? lq * s[i] * (G[i] - ms) : -3.0e38f;
                M = fmaxf(M, d[i]);
            }
            M = hmax8(M);

            float r = 0.f;
#pragma unroll
            for (int i = 0; i < 16; i++) {
                s[i] = s[i] * __expf(d[i] - M);
                r += s[i];
            }
            r = hsum8(r);
            float ir = 1.0f / r;

            float cd = 0.f;
#pragma unroll
            for (int i = 0; i < 16; i++) {
                s[i] *= ir;
                pacc[i] = fmaf(ql, s[i], pacc[i]);
                cd = fmaf(s[i], c[i], cd);
            }
            cacc = fmaf(ql, cd, cacc);

            if (!last) {
                *(float4*)&S[rl * NN + j0]      = make_float4(s[0], s[1], s[2], s[3]);
                *(float4*)&S[rl * NN + j0 + 4]  = make_float4(s[4], s[5], s[6], s[7]);
                *(float4*)&S[rl * NN + j0 + 8]  = make_float4(s[8], s[9], s[10], s[11]);
                *(float4*)&S[rl * NN + j0 + 12] = make_float4(s[12], s[13], s[14], s[15]);
            }
        }

        // combine p across the 4 row-groups of the warp (same columns)
#pragma unroll
        for (int i = 0; i < 16; i++) {
            pacc[i] += __shfl_xor_sync(0xffffffffu, pacc[i], 8);
            pacc[i] += __shfl_xor_sync(0xffffffffu, pacc[i], 16);
        }
        if (lane < 8) {
            *(float4*)&p_w[warp * NN + j0]      = make_float4(pacc[0], pacc[1], pacc[2], pacc[3]);
            *(float4*)&p_w[warp * NN + j0 + 4]  = make_float4(pacc[4], pacc[5], pacc[6], pacc[7]);
            *(float4*)&p_w[warp * NN + j0 + 8]  = make_float4(pacc[8], pacc[9], pacc[10], pacc[11]);
            *(float4*)&p_w[warp * NN + j0 + 12] = make_float4(pacc[12], pacc[13], pacc[14], pacc[15]);
        }
        cacc = wsum(cacc);
        if (lane == 0) cst[warp] = cacc;
        __syncthreads();

        float pj = 0.f;
        if (tid < NN)
            pj = p_w[tid] + p_w[NN + tid] + p_w[2 * NN + tid] + p_w[3 * NN + tid];

        if (last) {
            if (tid < NN) atomicAdd(&p_out[bk * NN + tid], pj);
            return;
        }

        int buf = it & 1;
        if (tid < NN) g_Pp[buf][(bk * 2 + half) * NN + tid] = pj;
        if (tid == 0)
            g_costp[buf][bk * 2 + half] = cst[0] + cst[1] + cst[2] + cst[3];
        __syncthreads();            // all global partial stores issued block-wide
        if (tid == 0) {
            __threadfence();        // release partials
            atomicAdd(&g_cnt[b], 1u);
            unsigned int target = 20u * (unsigned int)(it + 1);
            while (atomicAdd(&g_cnt[b], 0u) < target) __nanosleep(64);
            __threadfence();        // acquire peers' partials
            float cc = __ldcg(&g_costp[buf][bk * 2]) + __ldcg(&g_costp[buf][bk * 2 + 1]);
            float pen = cc - th;
            a_s = (pen > 0.f) ? (2.f * RHOc * pen) : 0.f;
        }
        __syncthreads();
        a = a_s;
        if (tid < NN) {
            float pv[KK];
            float mn = 3.402823466e38f;
#pragma unroll
            for (int kk = 0; kk < KK; kk++) {
                int bg = (b * KK + kk) * 2;
                pv[kk] = __ldcg(&g_Pp[buf][bg * NN + tid]) +
                         __ldcg(&g_Pp[buf][(bg + 1) * NN + tid]);
                mn = fminf(mn, pv[kk]);
            }
            float cnt2 = 0.f;
#pragma unroll
            for (int kk = 0; kk < KK; kk++) cnt2 += (pv[kk] == mn) ? 1.f : 0.f;
            w_s[tid] = (pv[k] == mn) ? (1.f / cnt2) : 0.f;
        }
        __syncthreads();
    }
}

extern "C" void kernel_launch(void* const* d_in, const int* in_sizes, int n_in,
                              void* d_out, int out_size) {
    const float* X     = (const float*)d_in[0];  // [32,128,512]
    const float* Qp    = (const float*)d_in[1];  // [32,10,128]
    const float* theta = (const float*)d_in[2];  // [32,10]
    float* out = (float*)d_out;                  // [32,10,128]

    proA_kernel<<<160, 256>>>(X, out);
    proB_kernel<<<BB, 256>>>(Qp, theta);
    solve_kernel<<<BB * KK * 2, 128>>>(Qp, theta, out);
}

// round 5
// speedup vs baseline: 1.2876x; 1.2876x over previous
#include <cuda_runtime.h>

#define BB 32
#define KK 10
#define NN 128
#define FF 512
#define NITER 30
#define LRc 0.5f
#define RHOc 10.0f

// ---- scratch (static device globals: allocation-free) ----
static __device__ float g_C[BB * NN * NN];          // 2 MB cost matrix
static __device__ float g_Pp[2][BB * KK * 2 * NN];  // double-buffered partial col sums
static __device__ float g_costp[2][BB * KK * 2];    // partial costs
static __device__ float g_a0[BB * KK];
static __device__ float g_xn[BB * NN];
static __device__ unsigned int g_cnt[BB];           // per-b monotonic barrier counter

__device__ __forceinline__ float wsum(float v) {
#pragma unroll
    for (int o = 16; o; o >>= 1) v += __shfl_xor_sync(0xffffffffu, v, o);
    return v;
}
__device__ __forceinline__ float hsum16(float v) {
#pragma unroll
    for (int o = 8; o; o >>= 1) v += __shfl_xor_sync(0xffffffffu, v, o);
    return v;
}
__device__ __forceinline__ float hmax16(float v) {
#pragma unroll
    for (int o = 8; o; o >>= 1) v = fmaxf(v, __shfl_xor_sync(0xffffffffu, v, o));
    return v;
}

// packed f32x2 helpers (Blackwell FFMA2)
__device__ __forceinline__ unsigned long long pk2(float lo, float hi) {
    unsigned long long r;
    asm("mov.b64 %0, {%1, %2};" : "=l"(r) : "f"(lo), "f"(hi));
    return r;
}
__device__ __forceinline__ void ffma2(unsigned long long& acc,
                                      unsigned long long a, unsigned long long b) {
    asm("fma.rn.f32x2 %0, %1, %2, %3;" : "=l"(acc) : "l"(a), "l"(b), "l"(acc));
}
__device__ __forceinline__ float pksum(unsigned long long v) {
    float lo, hi;
    asm("mov.b64 {%0, %1}, %2;" : "=f"(lo), "=f"(hi) : "l"(v));
    return lo + hi;
}

// ================= prologue A: gemm (bid<128) + xn & out-zero (bid>=128) ==========
__global__ void proA_kernel(const float* __restrict__ X, float* __restrict__ out) {
    if (blockIdx.x < 128) {
        int bid = blockIdx.x;
        int b = bid >> 2, q2 = bid & 3;
        int ti = (q2 >> 1) * 64, tj = (q2 & 1) * 64;
        __shared__ float As[16][64];
        __shared__ float Bs[16][64];
        const float* Xb = X + (size_t)b * NN * FF;
        int t = threadIdx.x;
        int lr = t >> 2, lq = t & 3;
        int tx = t & 15, ty = t >> 4;
        unsigned long long acc2[4][4];
#pragma unroll
        for (int i = 0; i < 4; i++)
#pragma unroll
            for (int j = 0; j < 4; j++) acc2[i][j] = 0ull;

        for (int kc = 0; kc < FF; kc += 16) {
            float4 av = *(const float4*)(Xb + (size_t)(ti + lr) * FF + kc + lq * 4);
            float4 bv = *(const float4*)(Xb + (size_t)(tj + lr) * FF + kc + lq * 4);
            if (kc) __syncthreads();
            As[lq * 4 + 0][lr] = av.x; As[lq * 4 + 1][lr] = av.y;
            As[lq * 4 + 2][lr] = av.z; As[lq * 4 + 3][lr] = av.w;
            Bs[lq * 4 + 0][lr] = bv.x; Bs[lq * 4 + 1][lr] = bv.y;
            Bs[lq * 4 + 2][lr] = bv.z; Bs[lq * 4 + 3][lr] = bv.w;
            __syncthreads();
#pragma unroll
            for (int kk = 0; kk < 16; kk += 2) {
                float4 a0 = *(const float4*)&As[kk][ty * 4];
                float4 a1 = *(const float4*)&As[kk + 1][ty * 4];
                float4 b0 = *(const float4*)&Bs[kk][tx * 4];
                float4 b1 = *(const float4*)&Bs[kk + 1][tx * 4];
                unsigned long long ap[4] = {pk2(a0.x, a1.x), pk2(a0.y, a1.y),
                                            pk2(a0.z, a1.z), pk2(a0.w, a1.w)};
                unsigned long long bp[4] = {pk2(b0.x, b1.x), pk2(b0.y, b1.y),
                                            pk2(b0.z, b1.z), pk2(b0.w, b1.w)};
#pragma unroll
                for (int i = 0; i < 4; i++)
#pragma unroll
                    for (int j = 0; j < 4; j++) ffma2(acc2[i][j], ap[i], bp[j]);
            }
        }
#pragma unroll
        for (int i = 0; i < 4; i++) {
            float4 o;
            o.x = pksum(acc2[i][0]); o.y = pksum(acc2[i][1]);
            o.z = pksum(acc2[i][2]); o.w = pksum(acc2[i][3]);
            *(float4*)(g_C + ((size_t)b * NN + ti + ty * 4 + i) * NN + tj + tx * 4) = o;
        }
    } else {
        int b = blockIdx.x - 128;
        int w = threadIdx.x >> 5, lane = threadIdx.x & 31;
        for (int l = w; l < NN; l += 8) {
            const float4* xr = (const float4*)(X + ((size_t)b * NN + l) * FF);
            float acc = 0.f;
#pragma unroll
            for (int q = 0; q < FF / 128; q++) {
                float4 v = xr[lane + 32 * q];
                acc += v.x * v.x + v.y * v.y + v.z * v.z + v.w * v.w;
            }
            acc = wsum(acc);
            if (lane == 0) g_xn[b * NN + l] = acc;
        }
        for (int i = threadIdx.x; i < KK * NN; i += 256)
            out[b * KK * NN + i] = 0.f;
    }
}

// ===== prologue B: C = clip(dist - diag_col, 0) in-place, row sums, a0, counter reset =====
__global__ void proB_kernel(const float* __restrict__ Q, const float* __restrict__ theta) {
    int b = blockIdx.x;
    __shared__ float xns[NN], dgv[NN], crow[NN];
    float* Gb = g_C + (size_t)b * NN * NN;
    int tid = threadIdx.x;
    if (tid < NN) {
        float xj = g_xn[b * NN + tid];
        xns[tid] = xj;
        dgv[tid] = xj + xj - 2.0f * Gb[tid * NN + tid];
    }
    __syncthreads();
    int w = tid >> 5, lane = tid & 31;
    for (int i = w; i < NN; i += 8) {
        float xi = xns[i];
        float4 g = *(float4*)(Gb + i * NN + lane * 4);
        float c0 = fmaxf(xi + xns[lane * 4 + 0] - 2.0f * g.x - dgv[lane * 4 + 0], 0.f);
        float c1 = fmaxf(xi + xns[lane * 4 + 1] - 2.0f * g.y - dgv[lane * 4 + 1], 0.f);
        float c2 = fmaxf(xi + xns[lane * 4 + 2] - 2.0f * g.z - dgv[lane * 4 + 2], 0.f);
        float c3 = fmaxf(xi + xns[lane * 4 + 3] - 2.0f * g.w - dgv[lane * 4 + 3], 0.f);
        *(float4*)(Gb + i * NN + lane * 4) = make_float4(c0, c1, c2, c3);
        float rs = wsum(c0 + c1 + c2 + c3);
        if (lane == 0) crow[i] = rs;
    }
    __syncthreads();
    for (int k = w; k < KK; k += 8) {
        float v = 0.f;
        const float* Qr = Q + (b * KK + k) * NN;
        for (int i = lane; i < NN; i += 32) v = fmaf(Qr[i], crow[i], v);
        v = wsum(v);
        if (lane == 0) {
            float pen = v * (1.0f / NN) - theta[b * KK + k];
            g_a0[b * KK + k] = (pen > 0.f) ? (2.f * RHOc * pen) : 0.f;
        }
    }
    if (tid == 0) g_cnt[b] = 0u;
}

// ====== persistent solver: 2 CTAs per (b,k), 128 threads, 8 cols/thread ======
__global__ void __launch_bounds__(128, 5) solve_kernel(
        const float* __restrict__ Q, const float* __restrict__ theta,
        float* __restrict__ p_out) {
    __shared__ float S[64 * NN];     // 32 KB: this half's softmax probs
    __shared__ float w_s[NN];
    __shared__ float q_s[64];
    __shared__ float p_w[4 * NN];
    __shared__ float cst[4];
    __shared__ float a_s;

    int tid = threadIdx.x, warp = tid >> 5, lane = tid & 31;
    int h = lane >> 4, hl = lane & 15;
    int j8 = hl * 8;
    int bkh = blockIdx.x, bk = bkh >> 1, half = bkh & 1;
    int b = bk / KK, k = bk - b * KK;

    const float* Cb = g_C + ((size_t)b * NN + half * 64) * NN;
    if (tid < 64) q_s[tid] = Q[bk * NN + half * 64 + tid];
    w_s[tid] = 0.f;                  // iter 0: constant w cancels in (G - <s,G>)
    float th = theta[bk];
    float a = g_a0[bk];
    __syncthreads();

    for (int it = 0; it < NITER; ++it) {
        const bool first = (it == 0);
        const bool last = (it == NITER - 1);
        float pacc[8];
#pragma unroll
        for (int i = 0; i < 8; i++) pacc[i] = 0.f;
        float cacc = 0.f;

#pragma unroll
        for (int p = 0; p < 8; ++p) {
            int l = p * 8 + warp * 2 + h;   // local row 0..63
            float ql = q_s[l];
            float4 ca = __ldg((const float4*)(Cb + l * NN + j8));
            float4 cb = __ldg((const float4*)(Cb + l * NN + j8 + 4));
            float c[8] = {ca.x, ca.y, ca.z, ca.w, cb.x, cb.y, cb.z, cb.w};
            float s[8];
            if (first) {
#pragma unroll
                for (int i = 0; i < 8; i++) s[i] = 0.0078125f;
            } else {
                float4 sa = *(float4*)&S[l * NN + j8];
                float4 sb = *(float4*)&S[l * NN + j8 + 4];
                s[0] = sa.x; s[1] = sa.y; s[2] = sa.z; s[3] = sa.w;
                s[4] = sb.x; s[5] = sb.y; s[6] = sb.z; s[7] = sb.w;
            }
            float4 wa = *(float4*)&w_s[j8];
            float4 wb = *(float4*)&w_s[j8 + 4];
            float wv[8] = {wa.x, wa.y, wa.z, wa.w, wb.x, wb.y, wb.z, wb.w};

            float G[8], ms = 0.f;
#pragma unroll
            for (int i = 0; i < 8; i++) {
                G[i] = fmaf(-a, c[i], wv[i]);
                ms = fmaf(s[i], G[i], ms);
            }
            ms = hsum16(ms);

            float lq = LRc * ql;
            float M = -3.0e38f;
#pragma unroll
            for (int i = 0; i < 8; i++) {
                G[i] = (s[i] > 0.f) ? lq * s[i] * (G[i] - ms) : -3.0e38f;  // reuse as d
                M = fmaxf(M, G[i]);
            }
            M = hmax16(M);

            float r = 0.f;
#pragma unroll
            for (int i = 0; i < 8; i++) {
                s[i] = s[i] * __expf(G[i] - M);
                r += s[i];
            }
            r = hsum16(r);
            float ir = 1.0f / r;

            float cd = 0.f;
#pragma unroll
            for (int i = 0; i < 8; i++) {
                s[i] *= ir;
                pacc[i] = fmaf(ql, s[i], pacc[i]);
                cd = fmaf(s[i], c[i], cd);
            }
            cacc = fmaf(ql, cd, cacc);

            if (!last) {
                *(float4*)&S[l * NN + j8]     = make_float4(s[0], s[1], s[2], s[3]);
                *(float4*)&S[l * NN + j8 + 4] = make_float4(s[4], s[5], s[6], s[7]);
            }
        }

        // combine p across the two half-lanes (h=0/h=1 hold different rows, same cols)
#pragma unroll
        for (int i = 0; i < 8; i++)
            pacc[i] += __shfl_xor_sync(0xffffffffu, pacc[i], 16);
        if (h == 0) {
            *(float4*)&p_w[warp * NN + j8]     = make_float4(pacc[0], pacc[1], pacc[2], pacc[3]);
            *(float4*)&p_w[warp * NN + j8 + 4] = make_float4(pacc[4], pacc[5], pacc[6], pacc[7]);
        }
        cacc = wsum(cacc);
        if (lane == 0) cst[warp] = cacc;
        __syncthreads();

        float pj = p_w[tid] + p_w[NN + tid] + p_w[2 * NN + tid] + p_w[3 * NN + tid];

        if (last) {
            atomicAdd(&p_out[bk * NN + tid], pj);
            return;
        }

        int buf = it & 1;
        g_Pp[buf][(bk * 2 + half) * NN + tid] = pj;
        if (tid == 0)
            g_costp[buf][bk * 2 + half] = cst[0] + cst[1] + cst[2] + cst[3];
        __syncthreads();            // all global partial stores issued block-wide
        if (tid == 0) {
            __threadfence();        // release partials
            atomicAdd(&g_cnt[b], 1u);
            unsigned int target = 20u * (unsigned int)(it + 1);
            while (atomicAdd(&g_cnt[b], 0u) < target) __nanosleep(64);
            __threadfence();        // acquire peers' partials
            float cc = __ldcg(&g_costp[buf][bk * 2]) + __ldcg(&g_costp[buf][bk * 2 + 1]);
            float pen = cc - th;
            a_s = (pen > 0.f) ? (2.f * RHOc * pen) : 0.f;
        }
        __syncthreads();
        a = a_s;
        {
            float pv[KK];
            float mn = 3.402823466e38f;
#pragma unroll
            for (int kk = 0; kk < KK; kk++) {
                int bg = (b * KK + kk) * 2;
                pv[kk] = __ldcg(&g_Pp[buf][bg * NN + tid]) +
                         __ldcg(&g_Pp[buf][(bg + 1) * NN + tid]);
                mn = fminf(mn, pv[kk]);
            }
            float cnt2 = 0.f;
#pragma unroll
            for (int kk = 0; kk < KK; kk++) cnt2 += (pv[kk] == mn) ? 1.f : 0.f;
            w_s[tid] = (pv[k] == mn) ? (1.f / cnt2) : 0.f;
        }
        __syncthreads();
    }
}

extern "C" void kernel_launch(void* const* d_in, const int* in_sizes, int n_in,
                              void* d_out, int out_size) {
    const float* X     = (const float*)d_in[0];  // [32,128,512]
    const float* Qp    = (const float*)d_in[1];  // [32,10,128]
    const float* theta = (const float*)d_in[2];  // [32,10]
    float* out = (float*)d_out;                  // [32,10,128]

    proA_kernel<<<160, 256>>>(X, out);
    proB_kernel<<<BB, 256>>>(Qp, theta);
    solve_kernel<<<BB * KK * 2, 128>>>(Qp, theta, out);
}

// round 6
// speedup vs baseline: 1.5898x; 1.2346x over previous
#include <cuda_runtime.h>
#include <cstdint>

#define BB 32
#define KK 10
#define NN 128
#define FF 512
#define NITER 30
#define LRc 0.5f
#define RHOc 10.0f

// ---- scratch (static device globals: allocation-free) ----
static __device__ float g_Gp[2][BB * NN * NN];   // 4 MB: two K-halves of X X^T
static __device__ float g_C[BB * NN * NN];       // 2 MB cost matrix
static __device__ float g_a0[BB * KK];
static __device__ float g_xn[BB * NN];

__device__ __forceinline__ float wsum(float v) {
#pragma unroll
    for (int o = 16; o; o >>= 1) v += __shfl_xor_sync(0xffffffffu, v, o);
    return v;
}
__device__ __forceinline__ float hsum16(float v) {
#pragma unroll
    for (int o = 8; o; o >>= 1) v += __shfl_xor_sync(0xffffffffu, v, o);
    return v;
}
__device__ __forceinline__ float hmax16(float v) {
#pragma unroll
    for (int o = 8; o; o >>= 1) v = fmaxf(v, __shfl_xor_sync(0xffffffffu, v, o));
    return v;
}
__device__ __forceinline__ uint32_t smem_u32(const void* p) {
    uint32_t a;
    asm("{ .reg .u64 t; cvta.to.shared.u64 t, %1; cvt.u32.u64 %0, t; }"
        : "=r"(a) : "l"(p));
    return a;
}
__device__ __forceinline__ float dsmem_ld(uint32_t addr, uint32_t rank) {
    uint32_t ra; float v;
    asm volatile("mapa.shared::cluster.u32 %0, %1, %2;" : "=r"(ra) : "r"(addr), "r"(rank));
    asm volatile("ld.shared::cluster.f32 %0, [%1];" : "=f"(v) : "r"(ra));
    return v;
}
#define CLUSTER_SYNC() do { \
    asm volatile("barrier.cluster.arrive.aligned;" ::: "memory"); \
    asm volatile("barrier.cluster.wait.aligned;" ::: "memory"); } while (0)

// ============ prologue A: gemm K-split (bid<256) + xn (bid>=256) ============
__global__ void proA_kernel(const float* __restrict__ X) {
    if (blockIdx.x < 256) {
        int bid = blockIdx.x;
        int b = bid >> 3, q2 = (bid >> 1) & 3, ks = bid & 1;
        int ti = (q2 >> 1) * 64, tj = (q2 & 1) * 64;
        __shared__ float As[16][64];
        __shared__ float Bs[16][64];
        const float* Xb = X + (size_t)b * NN * FF;
        int t = threadIdx.x;
        int lr = t >> 2, lq = t & 3;
        int tx = t & 15, ty = t >> 4;
        float acc[4][4];
#pragma unroll
        for (int i = 0; i < 4; i++)
#pragma unroll
            for (int j = 0; j < 4; j++) acc[i][j] = 0.f;

        for (int kc = ks * 256; kc < ks * 256 + 256; kc += 16) {
            float4 av = *(const float4*)(Xb + (size_t)(ti + lr) * FF + kc + lq * 4);
            float4 bv = *(const float4*)(Xb + (size_t)(tj + lr) * FF + kc + lq * 4);
            if (kc != ks * 256) __syncthreads();
            As[lq * 4 + 0][lr] = av.x; As[lq * 4 + 1][lr] = av.y;
            As[lq * 4 + 2][lr] = av.z; As[lq * 4 + 3][lr] = av.w;
            Bs[lq * 4 + 0][lr] = bv.x; Bs[lq * 4 + 1][lr] = bv.y;
            Bs[lq * 4 + 2][lr] = bv.z; Bs[lq * 4 + 3][lr] = bv.w;
            __syncthreads();
#pragma unroll
            for (int kk = 0; kk < 16; kk++) {
                float4 af = *(const float4*)&As[kk][ty * 4];
                float4 bf = *(const float4*)&Bs[kk][tx * 4];
                float a[4] = {af.x, af.y, af.z, af.w};
                float bb4[4] = {bf.x, bf.y, bf.z, bf.w};
#pragma unroll
                for (int i = 0; i < 4; i++)
#pragma unroll
                    for (int j = 0; j < 4; j++) acc[i][j] = fmaf(a[i], bb4[j], acc[i][j]);
            }
        }
#pragma unroll
        for (int i = 0; i < 4; i++) {
            float4 o; o.x = acc[i][0]; o.y = acc[i][1]; o.z = acc[i][2]; o.w = acc[i][3];
            *(float4*)(g_Gp[ks] + ((size_t)b * NN + ti + ty * 4 + i) * NN + tj + tx * 4) = o;
        }
    } else {
        int b = blockIdx.x - 256;
        int w = threadIdx.x >> 5, lane = threadIdx.x & 31;
        for (int l = w; l < NN; l += 8) {
            const float4* xr = (const float4*)(X + ((size_t)b * NN + l) * FF);
            float acc = 0.f;
#pragma unroll
            for (int q = 0; q < FF / 128; q++) {
                float4 v = xr[lane + 32 * q];
                acc += v.x * v.x + v.y * v.y + v.z * v.z + v.w * v.w;
            }
            acc = wsum(acc);
            if (lane == 0) g_xn[b * NN + l] = acc;
        }
    }
}

// ==== prologue B: G = G0+G1, C = clip(dist - diag_col, 0), row sums, a0 ====
__global__ void proB_kernel(const float* __restrict__ Q, const float* __restrict__ theta) {
    int b = blockIdx.x;
    __shared__ float xns[NN], dgv[NN], crow[NN];
    const float* G0 = g_Gp[0] + (size_t)b * NN * NN;
    const float* G1 = g_Gp[1] + (size_t)b * NN * NN;
    float* Cbo = g_C + (size_t)b * NN * NN;
    int tid = threadIdx.x;
    if (tid < NN) {
        float xj = g_xn[b * NN + tid];
        xns[tid] = xj;
        dgv[tid] = xj + xj - 2.0f * (G0[tid * NN + tid] + G1[tid * NN + tid]);
    }
    __syncthreads();
    int w = tid >> 5, lane = tid & 31;
    for (int i = w; i < NN; i += 8) {
        float xi = xns[i];
        float4 ga = *(const float4*)(G0 + i * NN + lane * 4);
        float4 gb = *(const float4*)(G1 + i * NN + lane * 4);
        float c0 = fmaxf(xi + xns[lane * 4 + 0] - 2.0f * (ga.x + gb.x) - dgv[lane * 4 + 0], 0.f);
        float c1 = fmaxf(xi + xns[lane * 4 + 1] - 2.0f * (ga.y + gb.y) - dgv[lane * 4 + 1], 0.f);
        float c2 = fmaxf(xi + xns[lane * 4 + 2] - 2.0f * (ga.z + gb.z) - dgv[lane * 4 + 2], 0.f);
        float c3 = fmaxf(xi + xns[lane * 4 + 3] - 2.0f * (ga.w + gb.w) - dgv[lane * 4 + 3], 0.f);
        *(float4*)(Cbo + i * NN + lane * 4) = make_float4(c0, c1, c2, c3);
        float rs = wsum(c0 + c1 + c2 + c3);
        if (lane == 0) crow[i] = rs;
    }
    __syncthreads();
    for (int k = w; k < KK; k += 8) {
        float v = 0.f;
        const float* Qr = Q + (b * KK + k) * NN;
        for (int i = lane; i < NN; i += 32) v = fmaf(Qr[i], crow[i], v);
        v = wsum(v);
        if (lane == 0) {
            float pen = v * (1.0f / NN) - theta[b * KK + k];
            g_a0[b * KK + k] = (pen > 0.f) ? (2.f * RHOc * pen) : 0.f;
        }
    }
}

// ===== persistent cluster solver: cluster of 10 CTAs per b, DSMEM p-exchange =====
#define SM_S    0
#define SM_W    16384
#define SM_Q    16512
#define SM_PW   16640
#define SM_PB   17664    /* [2][128] double-buffered p row */
#define SM_CST  17920    /* [8] */
#define SM_A    17928
#define SM_FLOATS 17932
#define SMEM_BYTES (SM_FLOATS * 4)

__global__ void __cluster_dims__(KK, 1, 1) __launch_bounds__(256, 3)
solve_kernel(const float* __restrict__ Q, const float* __restrict__ theta,
             float* __restrict__ p_out) {
    extern __shared__ float sm[];
    float* S   = sm + SM_S;
    float* w_s = sm + SM_W;
    float* q_s = sm + SM_Q;
    float* p_w = sm + SM_PW;
    float* pb  = sm + SM_PB;
    float* cst = sm + SM_CST;
    float* a_s = sm + SM_A;

    int k = blockIdx.x, b = blockIdx.y;
    int bk = b * KK + k;
    int tid = threadIdx.x;
    int warp = tid >> 5, lane = tid & 31;
    int h = lane >> 4, hl = lane & 15;
    int j0 = hl * 4, j1 = 64 + hl * 4;

    const float* Cb = g_C + (size_t)b * NN * NN;
    if (tid < NN) {
        q_s[tid] = Q[bk * NN + tid];
        w_s[tid] = 0.f;    // iter 0: constant w cancels in (G - <s,G>)
    }
    float th = theta[bk];
    float a = g_a0[bk];
    uint32_t pb_u32 = smem_u32(pb);
    __syncthreads();

    for (int it = 0; it < NITER; ++it) {
        const bool first = (it == 0);
        const bool last = (it == NITER - 1);
        float pacc[8];
#pragma unroll
        for (int i = 0; i < 8; i++) pacc[i] = 0.f;
        float cacc = 0.f;

#pragma unroll
        for (int pass = 0; pass < 8; ++pass) {
            int l = pass * 16 + warp * 2 + h;
            float ql = q_s[l];
            float4 ca = __ldg((const float4*)(Cb + l * NN + j0));
            float4 cb = __ldg((const float4*)(Cb + l * NN + j1));
            float c[8] = {ca.x, ca.y, ca.z, ca.w, cb.x, cb.y, cb.z, cb.w};
            float s[8];
            if (first) {
#pragma unroll
                for (int i = 0; i < 8; i++) s[i] = 0.0078125f;
            } else {
                float4 sa = *(float4*)&S[l * NN + j0];
                float4 sb = *(float4*)&S[l * NN + j1];
                s[0] = sa.x; s[1] = sa.y; s[2] = sa.z; s[3] = sa.w;
                s[4] = sb.x; s[5] = sb.y; s[6] = sb.z; s[7] = sb.w;
            }
            float4 wa = *(float4*)&w_s[j0];
            float4 wb = *(float4*)&w_s[j1];
            float wv[8] = {wa.x, wa.y, wa.z, wa.w, wb.x, wb.y, wb.z, wb.w};

            float G[8], ms = 0.f;
#pragma unroll
            for (int i = 0; i < 8; i++) {
                G[i] = fmaf(-a, c[i], wv[i]);
                ms = fmaf(s[i], G[i], ms);
            }
            ms = hsum16(ms);

            float lq = LRc * ql;
            float M = -3.0e38f;
#pragma unroll
            for (int i = 0; i < 8; i++) {
                G[i] = (s[i] > 0.f) ? lq * s[i] * (G[i] - ms) : -3.0e38f;  // reuse as d
                M = fmaxf(M, G[i]);
            }
            M = hmax16(M);

            float r = 0.f;
#pragma unroll
            for (int i = 0; i < 8; i++) {
                s[i] = s[i] * __expf(G[i] - M);
                r += s[i];
            }
            r = hsum16(r);
            float ir = 1.0f / r;

            float cd = 0.f;
#pragma unroll
            for (int i = 0; i < 8; i++) {
                s[i] *= ir;
                pacc[i] = fmaf(ql, s[i], pacc[i]);
                cd = fmaf(s[i], c[i], cd);
            }
            cacc = fmaf(ql, cd, cacc);

            if (!last) {
                *(float4*)&S[l * NN + j0] = make_float4(s[0], s[1], s[2], s[3]);
                *(float4*)&S[l * NN + j1] = make_float4(s[4], s[5], s[6], s[7]);
            }
        }

#pragma unroll
        for (int i = 0; i < 8; i++)
            pacc[i] += __shfl_xor_sync(0xffffffffu, pacc[i], 16);
        if (h == 0) {
            *(float4*)&p_w[warp * NN + j0] = make_float4(pacc[0], pacc[1], pacc[2], pacc[3]);
            *(float4*)&p_w[warp * NN + j1] = make_float4(pacc[4], pacc[5], pacc[6], pacc[7]);
        }
        cacc = wsum(cacc);
        if (lane == 0) cst[warp] = cacc;
        __syncthreads();

        float pj = 0.f;
        if (tid < NN) {
#pragma unroll
            for (int w2 = 0; w2 < 8; w2++) pj += p_w[w2 * NN + tid];
        }

        if (last) {
            if (tid < NN) p_out[bk * NN + tid] = pj;
            CLUSTER_SYNC();   // keep smem alive until peers' final DSMEM reads done
            return;
        }

        int buf = it & 1;
        if (tid < NN) pb[buf * NN + tid] = pj;
        if (tid == 0) {
            float cc = cst[0] + cst[1] + cst[2] + cst[3] +
                       cst[4] + cst[5] + cst[6] + cst[7];
            float pen = cc - th;
            a_s[0] = (pen > 0.f) ? (2.f * RHOc * pen) : 0.f;
        }
        __syncthreads();
        CLUSTER_SYNC();       // release own pb[buf], acquire peers' pb[buf]

        a = a_s[0];
        if (tid < NN) {
            uint32_t addr = pb_u32 + (uint32_t)(buf * NN + tid) * 4u;
            float pv[KK];
            float mn = 3.402823466e38f;
#pragma unroll
            for (int kk = 0; kk < KK; kk++) {
                pv[kk] = dsmem_ld(addr, (uint32_t)kk);
                mn = fminf(mn, pv[kk]);
            }
            float cnt2 = 0.f;
#pragma unroll
            for (int kk = 0; kk < KK; kk++) cnt2 += (pv[kk] == mn) ? 1.f : 0.f;
            w_s[tid] = (pv[k] == mn) ? (1.f / cnt2) : 0.f;
        }
        __syncthreads();
    }
}

extern "C" void kernel_launch(void* const* d_in, const int* in_sizes, int n_in,
                              void* d_out, int out_size) {
    const float* X     = (const float*)d_in[0];  // [32,128,512]
    const float* Qp    = (const float*)d_in[1];  // [32,10,128]
    const float* theta = (const float*)d_in[2];  // [32,10]
    float* out = (float*)d_out;                  // [32,10,128]

    cudaFuncSetAttribute(solve_kernel,
                         cudaFuncAttributeMaxDynamicSharedMemorySize, SMEM_BYTES);
    cudaFuncSetAttribute(solve_kernel,
                         cudaFuncAttributeNonPortableClusterSizeAllowed, 1);

    proA_kernel<<<288, 256>>>(X);
    proB_kernel<<<BB, 256>>>(Qp, theta);
    solve_kernel<<<dim3(KK, BB), 256, SMEM_BYTES>>>(Qp, theta, out);
}

// round 7
// speedup vs baseline: 1.6357x; 1.0289x over previous
#include <cuda_runtime.h>
#include <cstdint>

#define BB 32
#define KK 10
#define NN 128
#define FF 512
#define NITER 30
#define LRc 0.5f
#define RHOc 10.0f
#define LOG2E 1.4426950408889634f

// ---- scratch (static device globals: allocation-free) ----
static __device__ float g_Gp[4][BB * NN * NN];   // 8 MB: four K-quarters of X X^T
static __device__ float g_C[BB * NN * NN];       // 2 MB cost matrix
static __device__ float g_a0[BB * KK];
static __device__ float g_xn[BB * NN];

__device__ __forceinline__ float wsum(float v) {
#pragma unroll
    for (int o = 16; o; o >>= 1) v += __shfl_xor_sync(0xffffffffu, v, o);
    return v;
}
__device__ __forceinline__ float hsum16(float v) {
#pragma unroll
    for (int o = 8; o; o >>= 1) v += __shfl_xor_sync(0xffffffffu, v, o);
    return v;
}
__device__ __forceinline__ float hmax16(float v) {
#pragma unroll
    for (int o = 8; o; o >>= 1) v = fmaxf(v, __shfl_xor_sync(0xffffffffu, v, o));
    return v;
}
__device__ __forceinline__ float ex2(float x) {
    float r;
    asm("ex2.approx.f32 %0, %1;" : "=f"(r) : "f"(x));
    return r;
}
__device__ __forceinline__ uint32_t smem_u32(const void* p) {
    uint32_t a;
    asm("{ .reg .u64 t; cvta.to.shared.u64 t, %1; cvt.u32.u64 %0, t; }"
        : "=r"(a) : "l"(p));
    return a;
}
__device__ __forceinline__ float dsmem_ld(uint32_t addr, uint32_t rank) {
    uint32_t ra; float v;
    asm volatile("mapa.shared::cluster.u32 %0, %1, %2;" : "=r"(ra) : "r"(addr), "r"(rank));
    asm volatile("ld.shared::cluster.f32 %0, [%1];" : "=f"(v) : "r"(ra));
    return v;
}
__device__ __forceinline__ void mbar_init(uint32_t mbar, uint32_t count) {
    asm volatile("mbarrier.init.shared.b64 [%0], %1;" :: "r"(mbar), "r"(count) : "memory");
}
__device__ __forceinline__ void mbar_arrive_rank(uint32_t mbar, uint32_t rank) {
    asm volatile(
        "{ .reg .b32 ra; mapa.shared::cluster.u32 ra, %0, %1;\n\t"
        "mbarrier.arrive.release.cluster.shared::cluster.b64 _, [ra]; }"
        :: "r"(mbar), "r"(rank) : "memory");
}
__device__ __forceinline__ void mbar_wait(uint32_t mbar, uint32_t parity) {
    asm volatile(
        "{ .reg .pred P;\n\t"
        "WL_%=:\n\t"
        "mbarrier.try_wait.parity.acquire.cluster.shared::cta.b64 P, [%0], %1, 0x989680;\n\t"
        "@P bra.uni WD_%=;\n\t"
        "bra.uni WL_%=;\n\t"
        "WD_%=: }"
        :: "r"(mbar), "r"(parity) : "memory");
}
#define CLUSTER_SYNC() do { \
    asm volatile("barrier.cluster.arrive.aligned;" ::: "memory"); \
    asm volatile("barrier.cluster.wait.aligned;" ::: "memory"); } while (0)

// ============ prologue A: gemm K-split x4 (bid<512) + xn (bid>=512) ============
__global__ void proA_kernel(const float* __restrict__ X) {
    if (blockIdx.x < 512) {
        int bid = blockIdx.x;
        int b = bid >> 4, q2 = (bid >> 2) & 3, ks = bid & 3;
        int ti = (q2 >> 1) * 64, tj = (q2 & 1) * 64;
        __shared__ float As[16][64];
        __shared__ float Bs[16][64];
        const float* Xb = X + (size_t)b * NN * FF;
        int t = threadIdx.x;
        int lr = t >> 2, lq = t & 3;
        int tx = t & 15, ty = t >> 4;
        float acc[4][4];
#pragma unroll
        for (int i = 0; i < 4; i++)
#pragma unroll
            for (int j = 0; j < 4; j++) acc[i][j] = 0.f;

        for (int kc = ks * 128; kc < ks * 128 + 128; kc += 16) {
            float4 av = *(const float4*)(Xb + (size_t)(ti + lr) * FF + kc + lq * 4);
            float4 bv = *(const float4*)(Xb + (size_t)(tj + lr) * FF + kc + lq * 4);
            if (kc != ks * 128) __syncthreads();
            As[lq * 4 + 0][lr] = av.x; As[lq * 4 + 1][lr] = av.y;
            As[lq * 4 + 2][lr] = av.z; As[lq * 4 + 3][lr] = av.w;
            Bs[lq * 4 + 0][lr] = bv.x; Bs[lq * 4 + 1][lr] = bv.y;
            Bs[lq * 4 + 2][lr] = bv.z; Bs[lq * 4 + 3][lr] = bv.w;
            __syncthreads();
#pragma unroll
            for (int kk = 0; kk < 16; kk++) {
                float4 af = *(const float4*)&As[kk][ty * 4];
                float4 bf = *(const float4*)&Bs[kk][tx * 4];
                float a[4] = {af.x, af.y, af.z, af.w};
                float bb4[4] = {bf.x, bf.y, bf.z, bf.w};
#pragma unroll
                for (int i = 0; i < 4; i++)
#pragma unroll
                    for (int j = 0; j < 4; j++) acc[i][j] = fmaf(a[i], bb4[j], acc[i][j]);
            }
        }
#pragma unroll
        for (int i = 0; i < 4; i++) {
            float4 o; o.x = acc[i][0]; o.y = acc[i][1]; o.z = acc[i][2]; o.w = acc[i][3];
            *(float4*)(g_Gp[ks] + ((size_t)b * NN + ti + ty * 4 + i) * NN + tj + tx * 4) = o;
        }
    } else {
        int b = blockIdx.x - 512;
        int w = threadIdx.x >> 5, lane = threadIdx.x & 31;
        for (int l = w; l < NN; l += 8) {
            const float4* xr = (const float4*)(X + ((size_t)b * NN + l) * FF);
            float acc = 0.f;
#pragma unroll
            for (int q = 0; q < FF / 128; q++) {
                float4 v = xr[lane + 32 * q];
                acc += v.x * v.x + v.y * v.y + v.z * v.z + v.w * v.w;
            }
            acc = wsum(acc);
            if (lane == 0) g_xn[b * NN + l] = acc;
        }
    }
}

// ==== prologue B: G = sum of 4 parts, C = clip(dist - diag_col, 0), row sums, a0 ====
__global__ void proB_kernel(const float* __restrict__ Q, const float* __restrict__ theta) {
    int b = blockIdx.x;
    __shared__ float xns[NN], dgv[NN], crow[NN];
    const float* G0 = g_Gp[0] + (size_t)b * NN * NN;
    const float* G1 = g_Gp[1] + (size_t)b * NN * NN;
    const float* G2 = g_Gp[2] + (size_t)b * NN * NN;
    const float* G3 = g_Gp[3] + (size_t)b * NN * NN;
    float* Cbo = g_C + (size_t)b * NN * NN;
    int tid = threadIdx.x;
    if (tid < NN) {
        float xj = g_xn[b * NN + tid];
        xns[tid] = xj;
        float gd = G0[tid * NN + tid] + G1[tid * NN + tid] +
                   G2[tid * NN + tid] + G3[tid * NN + tid];
        dgv[tid] = xj + xj - 2.0f * gd;
    }
    __syncthreads();
    int w = tid >> 5, lane = tid & 31;
    for (int i = w; i < NN; i += 8) {
        float xi = xns[i];
        float4 ga = *(const float4*)(G0 + i * NN + lane * 4);
        float4 gb = *(const float4*)(G1 + i * NN + lane * 4);
        float4 gc = *(const float4*)(G2 + i * NN + lane * 4);
        float4 gd = *(const float4*)(G3 + i * NN + lane * 4);
        float s0 = ga.x + gb.x + gc.x + gd.x;
        float s1 = ga.y + gb.y + gc.y + gd.y;
        float s2 = ga.z + gb.z + gc.z + gd.z;
        float s3 = ga.w + gb.w + gc.w + gd.w;
        float c0 = fmaxf(xi + xns[lane * 4 + 0] - 2.0f * s0 - dgv[lane * 4 + 0], 0.f);
        float c1 = fmaxf(xi + xns[lane * 4 + 1] - 2.0f * s1 - dgv[lane * 4 + 1], 0.f);
        float c2 = fmaxf(xi + xns[lane * 4 + 2] - 2.0f * s2 - dgv[lane * 4 + 2], 0.f);
        float c3 = fmaxf(xi + xns[lane * 4 + 3] - 2.0f * s3 - dgv[lane * 4 + 3], 0.f);
        *(float4*)(Cbo + i * NN + lane * 4) = make_float4(c0, c1, c2, c3);
        float rs = wsum(c0 + c1 + c2 + c3);
        if (lane == 0) crow[i] = rs;
    }
    __syncthreads();
    for (int k = w; k < KK; k += 8) {
        float v = 0.f;
        const float* Qr = Q + (b * KK + k) * NN;
        for (int i = lane; i < NN; i += 32) v = fmaf(Qr[i], crow[i], v);
        v = wsum(v);
        if (lane == 0) {
            float pen = v * (1.0f / NN) - theta[b * KK + k];
            g_a0[b * KK + k] = (pen > 0.f) ? (2.f * RHOc * pen) : 0.f;
        }
    }
}

// ===== persistent cluster solver: cluster of 10 CTAs per b, mbarrier p-exchange =====
#define SM_S    0
#define SM_W    16384
#define SM_Q    16512
#define SM_PW   16640
#define SM_PB   17664    /* [2][128] double-buffered p row */
#define SM_CST  17920    /* [8] */
#define SM_A    17928
#define SM_MBAR 17930    /* 2 mbarriers (4 floats = 16B, 8-aligned) */
#define SM_FLOATS 17936
#define SMEM_BYTES (SM_FLOATS * 4)

__global__ void __cluster_dims__(KK, 1, 1) __launch_bounds__(256, 3)
solve_kernel(const float* __restrict__ Q, const float* __restrict__ theta,
             float* __restrict__ p_out) {
    extern __shared__ float sm[];
    float* S   = sm + SM_S;
    float* w_s = sm + SM_W;
    float* q_s = sm + SM_Q;
    float* p_w = sm + SM_PW;
    float* pb  = sm + SM_PB;
    float* cst = sm + SM_CST;
    float* a_s = sm + SM_A;

    int k = blockIdx.x, b = blockIdx.y;
    int bk = b * KK + k;
    int tid = threadIdx.x;
    int warp = tid >> 5, lane = tid & 31;
    int h = lane >> 4, hl = lane & 15;
    int j0 = hl * 4, j1 = 64 + hl * 4;

    const float* Cb = g_C + (size_t)b * NN * NN;
    uint32_t pb_u32 = smem_u32(pb);
    uint32_t mbar_u32 = smem_u32(sm + SM_MBAR);
    if (tid < NN) {
        q_s[tid] = Q[bk * NN + tid];
        w_s[tid] = 0.f;    // iter 0: constant w cancels in (G - <s,G>)
    }
    if (tid == 0) {
        mbar_init(mbar_u32, KK);       // barrier for even-buf exchanges
        mbar_init(mbar_u32 + 8, KK);   // barrier for odd-buf exchanges
    }
    float th = theta[bk];
    float a = g_a0[bk];
    __syncthreads();
    CLUSTER_SYNC();        // mbarrier init visible cluster-wide before first arrive

    for (int it = 0; it < NITER; ++it) {
        const bool first = (it == 0);
        const bool last = (it == NITER - 1);
        float pacc[8];
#pragma unroll
        for (int i = 0; i < 8; i++) pacc[i] = 0.f;
        float cacc = 0.f;

        // loop-invariant per-column w (register-resident for all passes)
        float4 wa = *(float4*)&w_s[j0];
        float4 wb = *(float4*)&w_s[j1];
        float wv[8] = {wa.x, wa.y, wa.z, wa.w, wb.x, wb.y, wb.z, wb.w};

#pragma unroll
        for (int pass = 0; pass < 4; ++pass) {
            int lA = pass * 32 + warp * 2 + h;
            int lB = lA + 16;
            float qlA = q_s[lA], qlB = q_s[lB];
            float4 cA0 = __ldg((const float4*)(Cb + lA * NN + j0));
            float4 cA1 = __ldg((const float4*)(Cb + lA * NN + j1));
            float4 cB0 = __ldg((const float4*)(Cb + lB * NN + j0));
            float4 cB1 = __ldg((const float4*)(Cb + lB * NN + j1));
            float cA[8] = {cA0.x, cA0.y, cA0.z, cA0.w, cA1.x, cA1.y, cA1.z, cA1.w};
            float cB[8] = {cB0.x, cB0.y, cB0.z, cB0.w, cB1.x, cB1.y, cB1.z, cB1.w};
            float sA[8], sB[8];
            if (first) {
#pragma unroll
                for (int i = 0; i < 8; i++) { sA[i] = 0.0078125f; sB[i] = 0.0078125f; }
            } else {
                float4 t0 = *(float4*)&S[lA * NN + j0];
                float4 t1 = *(float4*)&S[lA * NN + j1];
                float4 t2 = *(float4*)&S[lB * NN + j0];
                float4 t3 = *(float4*)&S[lB * NN + j1];
                sA[0] = t0.x; sA[1] = t0.y; sA[2] = t0.z; sA[3] = t0.w;
                sA[4] = t1.x; sA[5] = t1.y; sA[6] = t1.z; sA[7] = t1.w;
                sB[0] = t2.x; sB[1] = t2.y; sB[2] = t2.z; sB[3] = t2.w;
                sB[4] = t3.x; sB[5] = t3.y; sB[6] = t3.z; sB[7] = t3.w;
            }

            float GA[8], GB[8], msA = 0.f, msB = 0.f;
#pragma unroll
            for (int i = 0; i < 8; i++) {
                GA[i] = fmaf(-a, cA[i], wv[i]);
                GB[i] = fmaf(-a, cB[i], wv[i]);
                msA = fmaf(sA[i], GA[i], msA);
                msB = fmaf(sB[i], GB[i], msB);
            }
            msA = hsum16(msA);
            msB = hsum16(msB);

            float lqA = LRc * LOG2E * qlA;
            float lqB = LRc * LOG2E * qlB;
            float MA = -3.0e38f, MB = -3.0e38f;
#pragma unroll
            for (int i = 0; i < 8; i++) {
                GA[i] = (sA[i] > 0.f) ? lqA * sA[i] * (GA[i] - msA) : -3.0e38f;
                GB[i] = (sB[i] > 0.f) ? lqB * sB[i] * (GB[i] - msB) : -3.0e38f;
                MA = fmaxf(MA, GA[i]);
                MB = fmaxf(MB, GB[i]);
            }
            MA = hmax16(MA);
            MB = hmax16(MB);

            float rA = 0.f, rB = 0.f;
#pragma unroll
            for (int i = 0; i < 8; i++) {
                sA[i] = sA[i] * ex2(GA[i] - MA);
                sB[i] = sB[i] * ex2(GB[i] - MB);
                rA += sA[i];
                rB += sB[i];
            }
            rA = hsum16(rA);
            rB = hsum16(rB);
            float irA = 1.0f / rA, irB = 1.0f / rB;

            float cdA = 0.f, cdB = 0.f;
#pragma unroll
            for (int i = 0; i < 8; i++) {
                sA[i] *= irA;
                sB[i] *= irB;
                pacc[i] = fmaf(qlA, sA[i], pacc[i]);
                pacc[i] = fmaf(qlB, sB[i], pacc[i]);
                cdA = fmaf(sA[i], cA[i], cdA);
                cdB = fmaf(sB[i], cB[i], cdB);
            }
            cacc = fmaf(qlA, cdA, cacc);
            cacc = fmaf(qlB, cdB, cacc);

            if (!last) {
                *(float4*)&S[lA * NN + j0] = make_float4(sA[0], sA[1], sA[2], sA[3]);
                *(float4*)&S[lA * NN + j1] = make_float4(sA[4], sA[5], sA[6], sA[7]);
                *(float4*)&S[lB * NN + j0] = make_float4(sB[0], sB[1], sB[2], sB[3]);
                *(float4*)&S[lB * NN + j1] = make_float4(sB[4], sB[5], sB[6], sB[7]);
            }
        }

#pragma unroll
        for (int i = 0; i < 8; i++)
            pacc[i] += __shfl_xor_sync(0xffffffffu, pacc[i], 16);
        if (h == 0) {
            *(float4*)&p_w[warp * NN + j0] = make_float4(pacc[0], pacc[1], pacc[2], pacc[3]);
            *(float4*)&p_w[warp * NN + j1] = make_float4(pacc[4], pacc[5], pacc[6], pacc[7]);
        }
        cacc = wsum(cacc);
        if (lane == 0) cst[warp] = cacc;
        __syncthreads();

        float pj = 0.f;
        if (tid < NN) {
#pragma unroll
            for (int w2 = 0; w2 < 8; w2++) pj += p_w[w2 * NN + tid];
        }

        if (last) {
            if (tid < NN) p_out[bk * NN + tid] = pj;
            CLUSTER_SYNC();   // keep smem alive until peers' final DSMEM reads done
            return;
        }

        int buf = it & 1;
        if (tid < NN) pb[buf * NN + tid] = pj;
        if (tid == 0) {
            float cc = cst[0] + cst[1] + cst[2] + cst[3] +
                       cst[4] + cst[5] + cst[6] + cst[7];
            float pen = cc - th;
            a_s[0] = (pen > 0.f) ? (2.f * RHOc * pen) : 0.f;
        }
        __syncthreads();                       // pb + a_s visible CTA-wide
        if (tid < KK) mbar_arrive_rank(mbar_u32 + buf * 8, (uint32_t)tid);
        mbar_wait(mbar_u32 + buf * 8, (uint32_t)((it >> 1) & 1));

        a = a_s[0];
        if (tid < NN) {
            uint32_t addr = pb_u32 + (uint32_t)(buf * NN + tid) * 4u;
            float pv[KK];
            float mn = 3.402823466e38f;
#pragma unroll
            for (int kk = 0; kk < KK; kk++) {
                pv[kk] = dsmem_ld(addr, (uint32_t)kk);
                mn = fminf(mn, pv[kk]);
            }
            float cnt2 = 0.f;
#pragma unroll
            for (int kk = 0; kk < KK; kk++) cnt2 += (pv[kk] == mn) ? 1.f : 0.f;
            w_s[tid] = (pv[k] == mn) ? (1.f / cnt2) : 0.f;
        }
        __syncthreads();
    }
}

extern "C" void kernel_launch(void* const* d_in, const int* in_sizes, int n_in,
                              void* d_out, int out_size) {
    const float* X     = (const float*)d_in[0];  // [32,128,512]
    const float* Qp    = (const float*)d_in[1];  // [32,10,128]
    const float* theta = (const float*)d_in[2];  // [32,10]
    float* out = (float*)d_out;                  // [32,10,128]

    cudaFuncSetAttribute(solve_kernel,
                         cudaFuncAttributeMaxDynamicSharedMemorySize, SMEM_BYTES);
    cudaFuncSetAttribute(solve_kernel,
                         cudaFuncAttributeNonPortableClusterSizeAllowed, 1);

    proA_kernel<<<544, 256>>>(X);
    proB_kernel<<<BB, 256>>>(Qp, theta);
    solve_kernel<<<dim3(KK, BB), 256, SMEM_BYTES>>>(Qp, theta, out);
}

// round 8
// speedup vs baseline: 1.9564x; 1.1961x over previous
#include <cuda_runtime.h>
#include <cstdint>

#define BB 32
#define KK 10
#define NN 128
#define FF 512
#define NITER 30
#define LRc 0.5f
#define RHOc 10.0f
#define LOG2E 1.4426950408889634f

typedef unsigned long long u64;

// ---- scratch (static device globals: allocation-free) ----
static __device__ float g_Gp[4][BB * NN * NN];   // 8 MB: four K-quarters of X X^T
static __device__ float g_C[BB * NN * NN];       // 2 MB cost matrix
static __device__ float g_a0[BB * KK];
static __device__ float g_xn[BB * NN];

__device__ __forceinline__ float wsum(float v) {
#pragma unroll
    for (int o = 16; o; o >>= 1) v += __shfl_xor_sync(0xffffffffu, v, o);
    return v;
}
__device__ __forceinline__ float hsum16(float v) {
#pragma unroll
    for (int o = 8; o; o >>= 1) v += __shfl_xor_sync(0xffffffffu, v, o);
    return v;
}
__device__ __forceinline__ float hmax16(float v) {
#pragma unroll
    for (int o = 8; o; o >>= 1) v = fmaxf(v, __shfl_xor_sync(0xffffffffu, v, o));
    return v;
}
__device__ __forceinline__ float ex2(float x) {
    float r;
    asm("ex2.approx.f32 %0, %1;" : "=f"(r) : "f"(x));
    return r;
}
__device__ __forceinline__ float rcpa(float x) {
    float r;
    asm("rcp.approx.f32 %0, %1;" : "=f"(r) : "f"(x));
    return r;
}
// ---- packed f32x2 ----
__device__ __forceinline__ u64 pk(float lo, float hi) {
    u64 r;
    asm("mov.b64 %0, {%1, %2};" : "=l"(r) : "f"(lo), "f"(hi));
    return r;
}
__device__ __forceinline__ void upk(float& lo, float& hi, u64 v) {
    asm("mov.b64 {%0, %1}, %2;" : "=f"(lo), "=f"(hi) : "l"(v));
}
__device__ __forceinline__ u64 fma2(u64 a, u64 b, u64 c) {
    u64 d;
    asm("fma.rn.f32x2 %0, %1, %2, %3;" : "=l"(d) : "l"(a), "l"(b), "l"(c));
    return d;
}
__device__ __forceinline__ u64 mul2(u64 a, u64 b) {
    u64 d;
    asm("mul.rn.f32x2 %0, %1, %2;" : "=l"(d) : "l"(a), "l"(b));
    return d;
}
__device__ __forceinline__ u64 add2(u64 a, u64 b) {
    u64 d;
    asm("add.rn.f32x2 %0, %1, %2;" : "=l"(d) : "l"(a), "l"(b));
    return d;
}
__device__ __forceinline__ uint32_t smem_u32(const void* p) {
    uint32_t a;
    asm("{ .reg .u64 t; cvta.to.shared.u64 t, %1; cvt.u32.u64 %0, t; }"
        : "=r"(a) : "l"(p));
    return a;
}
__device__ __forceinline__ float dsmem_ld(uint32_t addr, uint32_t rank) {
    uint32_t ra; float v;
    asm volatile("mapa.shared::cluster.u32 %0, %1, %2;" : "=r"(ra) : "r"(addr), "r"(rank));
    asm volatile("ld.shared::cluster.f32 %0, [%1];" : "=f"(v) : "r"(ra));
    return v;
}
__device__ __forceinline__ void mbar_init(uint32_t mbar, uint32_t count) {
    asm volatile("mbarrier.init.shared.b64 [%0], %1;" :: "r"(mbar), "r"(count) : "memory");
}
__device__ __forceinline__ void mbar_arrive_rank(uint32_t mbar, uint32_t rank) {
    asm volatile(
        "{ .reg .b32 ra; mapa.shared::cluster.u32 ra, %0, %1;\n\t"
        "mbarrier.arrive.release.cluster.shared::cluster.b64 _, [ra]; }"
        :: "r"(mbar), "r"(rank) : "memory");
}
__device__ __forceinline__ void mbar_wait(uint32_t mbar, uint32_t parity) {
    asm volatile(
        "{ .reg .pred P;\n\t"
        "WL_%=:\n\t"
        "mbarrier.try_wait.parity.acquire.cluster.shared::cta.b64 P, [%0], %1, 0x989680;\n\t"
        "@P bra.uni WD_%=;\n\t"
        "bra.uni WL_%=;\n\t"
        "WD_%=: }"
        :: "r"(mbar), "r"(parity) : "memory");
}
#define CLUSTER_SYNC() do { \
    asm volatile("barrier.cluster.arrive.aligned;" ::: "memory"); \
    asm volatile("barrier.cluster.wait.aligned;" ::: "memory"); } while (0)

// ============ prologue A: gemm K-split x4 (bid<512) + xn (bid>=512) ============
__global__ void proA_kernel(const float* __restrict__ X) {
    if (blockIdx.x < 512) {
        int bid = blockIdx.x;
        int b = bid >> 4, q2 = (bid >> 2) & 3, ks = bid & 3;
        int ti = (q2 >> 1) * 64, tj = (q2 & 1) * 64;
        __shared__ float As[16][64];
        __shared__ float Bs[16][64];
        const float* Xb = X + (size_t)b * NN * FF;
        int t = threadIdx.x;
        int lr = t >> 2, lq = t & 3;
        int tx = t & 15, ty = t >> 4;
        float acc[4][4];
#pragma unroll
        for (int i = 0; i < 4; i++)
#pragma unroll
            for (int j = 0; j < 4; j++) acc[i][j] = 0.f;

        for (int kc = ks * 128; kc < ks * 128 + 128; kc += 16) {
            float4 av = *(const float4*)(Xb + (size_t)(ti + lr) * FF + kc + lq * 4);
            float4 bv = *(const float4*)(Xb + (size_t)(tj + lr) * FF + kc + lq * 4);
            if (kc != ks * 128) __syncthreads();
            As[lq * 4 + 0][lr] = av.x; As[lq * 4 + 1][lr] = av.y;
            As[lq * 4 + 2][lr] = av.z; As[lq * 4 + 3][lr] = av.w;
            Bs[lq * 4 + 0][lr] = bv.x; Bs[lq * 4 + 1][lr] = bv.y;
            Bs[lq * 4 + 2][lr] = bv.z; Bs[lq * 4 + 3][lr] = bv.w;
            __syncthreads();
#pragma unroll
            for (int kk = 0; kk < 16; kk++) {
                float4 af = *(const float4*)&As[kk][ty * 4];
                float4 bf = *(const float4*)&Bs[kk][tx * 4];
                float a[4] = {af.x, af.y, af.z, af.w};
                float bb4[4] = {bf.x, bf.y, bf.z, bf.w};
#pragma unroll
                for (int i = 0; i < 4; i++)
#pragma unroll
                    for (int j = 0; j < 4; j++) acc[i][j] = fmaf(a[i], bb4[j], acc[i][j]);
            }
        }
#pragma unroll
        for (int i = 0; i < 4; i++) {
            float4 o; o.x = acc[i][0]; o.y = acc[i][1]; o.z = acc[i][2]; o.w = acc[i][3];
            *(float4*)(g_Gp[ks] + ((size_t)b * NN + ti + ty * 4 + i) * NN + tj + tx * 4) = o;
        }
    } else {
        int b = blockIdx.x - 512;
        int w = threadIdx.x >> 5, lane = threadIdx.x & 31;
        for (int l = w; l < NN; l += 8) {
            const float4* xr = (const float4*)(X + ((size_t)b * NN + l) * FF);
            float acc = 0.f;
#pragma unroll
            for (int q = 0; q < FF / 128; q++) {
                float4 v = xr[lane + 32 * q];
                acc += v.x * v.x + v.y * v.y + v.z * v.z + v.w * v.w;
            }
            acc = wsum(acc);
            if (lane == 0) g_xn[b * NN + l] = acc;
        }
    }
}

// ==== prologue B: G = sum of 4 parts, C = clip(dist - diag_col, 0), row sums, a0 ====
__global__ void proB_kernel(const float* __restrict__ Q, const float* __restrict__ theta) {
    int b = blockIdx.x;
    __shared__ float xns[NN], dgv[NN], crow[NN];
    const float* G0 = g_Gp[0] + (size_t)b * NN * NN;
    const float* G1 = g_Gp[1] + (size_t)b * NN * NN;
    const float* G2 = g_Gp[2] + (size_t)b * NN * NN;
    const float* G3 = g_Gp[3] + (size_t)b * NN * NN;
    float* Cbo = g_C + (size_t)b * NN * NN;
    int tid = threadIdx.x;
    if (tid < NN) {
        float xj = g_xn[b * NN + tid];
        xns[tid] = xj;
        float gd = G0[tid * NN + tid] + G1[tid * NN + tid] +
                   G2[tid * NN + tid] + G3[tid * NN + tid];
        dgv[tid] = xj + xj - 2.0f * gd;
    }
    __syncthreads();
    int w = tid >> 5, lane = tid & 31;
    for (int i = w; i < NN; i += 8) {
        float xi = xns[i];
        float4 ga = *(const float4*)(G0 + i * NN + lane * 4);
        float4 gb = *(const float4*)(G1 + i * NN + lane * 4);
        float4 gc = *(const float4*)(G2 + i * NN + lane * 4);
        float4 gd = *(const float4*)(G3 + i * NN + lane * 4);
        float s0 = ga.x + gb.x + gc.x + gd.x;
        float s1 = ga.y + gb.y + gc.y + gd.y;
        float s2 = ga.z + gb.z + gc.z + gd.z;
        float s3 = ga.w + gb.w + gc.w + gd.w;
        float c0 = fmaxf(xi + xns[lane * 4 + 0] - 2.0f * s0 - dgv[lane * 4 + 0], 0.f);
        float c1 = fmaxf(xi + xns[lane * 4 + 1] - 2.0f * s1 - dgv[lane * 4 + 1], 0.f);
        float c2 = fmaxf(xi + xns[lane * 4 + 2] - 2.0f * s2 - dgv[lane * 4 + 2], 0.f);
        float c3 = fmaxf(xi + xns[lane * 4 + 3] - 2.0f * s3 - dgv[lane * 4 + 3], 0.f);
        *(float4*)(Cbo + i * NN + lane * 4) = make_float4(c0, c1, c2, c3);
        float rs = wsum(c0 + c1 + c2 + c3);
        if (lane == 0) crow[i] = rs;
    }
    __syncthreads();
    for (int k = w; k < KK; k += 8) {
        float v = 0.f;
        const float* Qr = Q + (b * KK + k) * NN;
        for (int i = lane; i < NN; i += 32) v = fmaf(Qr[i], crow[i], v);
        v = wsum(v);
        if (lane == 0) {
            float pen = v * (1.0f / NN) - theta[b * KK + k];
            g_a0[b * KK + k] = (pen > 0.f) ? (2.f * RHOc * pen) : 0.f;
        }
    }
}

// ===== persistent cluster solver: cluster of 10 CTAs per b, packed f32x2 math =====
#define SM_S    0
#define SM_W    16384
#define SM_Q    16512
#define SM_PW   16640
#define SM_PB   17664    /* [2][128] double-buffered p row */
#define SM_CST  17920    /* [8] */
#define SM_A    17928
#define SM_MBAR 17930    /* 2 mbarriers (16B, 8-aligned) */
#define SM_FLOATS 17936
#define SMEM_BYTES (SM_FLOATS * 4)

__global__ void __cluster_dims__(KK, 1, 1) __launch_bounds__(256, 3)
solve_kernel(const float* __restrict__ Q, const float* __restrict__ theta,
             float* __restrict__ p_out) {
    extern __shared__ float sm[];
    float* S   = sm + SM_S;
    float* w_s = sm + SM_W;
    float* q_s = sm + SM_Q;
    float* p_w = sm + SM_PW;
    float* pb  = sm + SM_PB;
    float* cst = sm + SM_CST;
    float* a_s = sm + SM_A;

    int k = blockIdx.x, b = blockIdx.y;
    int bk = b * KK + k;
    int tid = threadIdx.x;
    int warp = tid >> 5, lane = tid & 31;
    int h = lane >> 4, hl = lane & 15;
    int j0 = hl * 4, j1 = 64 + hl * 4;

    const float* Cb = g_C + (size_t)b * NN * NN;
    uint32_t pb_u32 = smem_u32(pb);
    uint32_t mbar_u32 = smem_u32(sm + SM_MBAR);
    if (tid < NN) {
        q_s[tid] = Q[bk * NN + tid];
        w_s[tid] = 0.f;    // iter 0: constant w cancels in (G - <s,G>)
    }
    if (tid == 0) {
        mbar_init(mbar_u32, KK);
        mbar_init(mbar_u32 + 8, KK);
    }
    float th = theta[bk];
    float a = g_a0[bk];
    __syncthreads();
    CLUSTER_SYNC();        // mbarrier init visible cluster-wide before first arrive

    for (int it = 0; it < NITER; ++it) {
        const bool first = (it == 0);
        const bool last = (it == NITER - 1);

        u64 na2 = pk(-a, -a);
        // loop-invariant per-column w (register-resident for all passes)
        ulonglong2 wva = *(ulonglong2*)&w_s[j0];
        ulonglong2 wvb = *(ulonglong2*)&w_s[j1];
        u64 w2[4] = {wva.x, wva.y, wvb.x, wvb.y};

        u64 pacc2[4] = {0ull, 0ull, 0ull, 0ull};
        u64 cacc2 = 0ull;

#pragma unroll
        for (int pass = 0; pass < 8; ++pass) {
            int l = pass * 16 + warp * 2 + h;
            float ql = q_s[l];
            ulonglong2 cva = *(const ulonglong2*)(Cb + l * NN + j0);
            ulonglong2 cvb = *(const ulonglong2*)(Cb + l * NN + j1);
            u64 c2[4] = {cva.x, cva.y, cvb.x, cvb.y};
            u64 s2[4];
            if (first) {
                u64 u = pk(0.0078125f, 0.0078125f);
#pragma unroll
                for (int i = 0; i < 4; i++) s2[i] = u;
            } else {
                ulonglong2 sva = *(ulonglong2*)&S[l * NN + j0];
                ulonglong2 svb = *(ulonglong2*)&S[l * NN + j1];
                s2[0] = sva.x; s2[1] = sva.y; s2[2] = svb.x; s2[3] = svb.y;
            }

            u64 G2[4], msp = 0ull;
#pragma unroll
            for (int i = 0; i < 4; i++) {
                G2[i] = fma2(na2, c2[i], w2[i]);
                msp = fma2(s2[i], G2[i], msp);
            }
            float mlo, mhi;
            upk(mlo, mhi, msp);
            float ms = hsum16(mlo + mhi);
            u64 nms2 = pk(-ms, -ms);

            float lq = (LRc * LOG2E) * ql;
            u64 lq2 = pk(lq, lq);
            u64 d2[4];
#pragma unroll
            for (int i = 0; i < 4; i++)
                d2[i] = mul2(lq2, mul2(s2[i], add2(G2[i], nms2)));

            float d[8];
            upk(d[0], d[1], d2[0]);
            upk(d[2], d[3], d2[1]);
            upk(d[4], d[5], d2[2]);
            upk(d[6], d[7], d2[3]);
            float M = fmaxf(fmaxf(fmaxf(d[0], d[1]), fmaxf(d[2], d[3])),
                            fmaxf(fmaxf(d[4], d[5]), fmaxf(d[6], d[7])));
            M = hmax16(M);

            float x[8];
#pragma unroll
            for (int i = 0; i < 8; i++) x[i] = ex2(d[i] - M);
            u64 x2[4] = {pk(x[0], x[1]), pk(x[2], x[3]),
                         pk(x[4], x[5]), pk(x[6], x[7])};

            u64 e2[4], rp = 0ull;
#pragma unroll
            for (int i = 0; i < 4; i++) {
                e2[i] = mul2(s2[i], x2[i]);
                rp = add2(rp, e2[i]);
            }
            float rlo, rhi;
            upk(rlo, rhi, rp);
            float r = hsum16(rlo + rhi);
            float ir = rcpa(r);
            u64 ir2 = pk(ir, ir);
            u64 ql2 = pk(ql, ql);

            u64 cdp = 0ull;
#pragma unroll
            for (int i = 0; i < 4; i++) {
                s2[i] = mul2(e2[i], ir2);
                pacc2[i] = fma2(ql2, s2[i], pacc2[i]);
                cdp = fma2(s2[i], c2[i], cdp);
            }
            cacc2 = fma2(ql2, cdp, cacc2);

            if (!last) {
                *(ulonglong2*)&S[l * NN + j0] = make_ulonglong2(s2[0], s2[1]);
                *(ulonglong2*)&S[l * NN + j1] = make_ulonglong2(s2[2], s2[3]);
            }
        }

        // combine p across the two half-lanes (h=0/h=1 hold different rows, same cols)
#pragma unroll
        for (int i = 0; i < 4; i++) {
            u64 o = __shfl_xor_sync(0xffffffffu, pacc2[i], 16);
            pacc2[i] = add2(pacc2[i], o);
        }
        if (h == 0) {
            *(ulonglong2*)&p_w[warp * NN + j0] = make_ulonglong2(pacc2[0], pacc2[1]);
            *(ulonglong2*)&p_w[warp * NN + j1] = make_ulonglong2(pacc2[2], pacc2[3]);
        }
        float clo, chi;
        upk(clo, chi, cacc2);
        float cacc = wsum(clo + chi);
        if (lane == 0) cst[warp] = cacc;
        __syncthreads();

        float pj = 0.f;
        if (tid < NN) {
#pragma unroll
            for (int w2i = 0; w2i < 8; w2i++) pj += p_w[w2i * NN + tid];
        }

        if (last) {
            if (tid < NN) p_out[bk * NN + tid] = pj;
            CLUSTER_SYNC();   // keep smem alive until peers' final DSMEM reads done
            return;
        }

        int buf = it & 1;
        if (tid < NN) pb[buf * NN + tid] = pj;
        if (tid == 0) {
            float cc = cst[0] + cst[1] + cst[2] + cst[3] +
                       cst[4] + cst[5] + cst[6] + cst[7];
            float pen = cc - th;
            a_s[0] = (pen > 0.f) ? (2.f * RHOc * pen) : 0.f;
        }
        __syncthreads();                       // pb + a_s visible CTA-wide
        if (tid < KK) mbar_arrive_rank(mbar_u32 + buf * 8, (uint32_t)tid);
        mbar_wait(mbar_u32 + buf * 8, (uint32_t)((it >> 1) & 1));

        a = a_s[0];
        if (tid < NN) {
            uint32_t addr = pb_u32 + (uint32_t)(buf * NN + tid) * 4u;
            float pv[KK];
            float mn = 3.402823466e38f;
#pragma unroll
            for (int kk = 0; kk < KK; kk++) {
                pv[kk] = dsmem_ld(addr, (uint32_t)kk);
                mn = fminf(mn, pv[kk]);
            }
            float cnt2 = 0.f;
#pragma unroll
            for (int kk = 0; kk < KK; kk++) cnt2 += (pv[kk] == mn) ? 1.f : 0.f;
            w_s[tid] = (pv[k] == mn) ? (1.f / cnt2) : 0.f;
        }
        __syncthreads();
    }
}

extern "C" void kernel_launch(void* const* d_in, const int* in_sizes, int n_in,
                              void* d_out, int out_size) {
    const float* X     = (const float*)d_in[0];  // [32,128,512]
    const float* Qp    = (const float*)d_in[1];  // [32,10,128]
    const float* theta = (const float*)d_in[2];  // [32,10]
    float* out = (float*)d_out;                  // [32,10,128]

    cudaFuncSetAttribute(solve_kernel,
                         cudaFuncAttributeMaxDynamicSharedMemorySize, SMEM_BYTES);
    cudaFuncSetAttribute(solve_kernel,
                         cudaFuncAttributeNonPortableClusterSizeAllowed, 1);

    proA_kernel<<<544, 256>>>(X);
    proB_kernel<<<BB, 256>>>(Qp, theta);
    solve_kernel<<<dim3(KK, BB), 256, SMEM_BYTES>>>(Qp, theta, out);
}